// round 16
// baseline (speedup 1.0000x reference)
#include <cuda_runtime.h>
#include <math.h>

#define KW   9
#define PAD  4
#define TXL  32
#define TYL  2
#define PXT  2
#define TW   64
#define TH   2
#define SXU  (TW + 2*PAD)  // 72
#define SXP  76            // padded row stride
#define HH   256
#define WW   256
#define CC   3

#define INV_DIAG (1.0f / 362.03867196751236f)
#define SIGMA_MIN 0.5f
#define SIGMA_RANGE 9.5f
#define PI_F 3.14159265358979323846f

// rows 0..4 of the symmetric 9x9 q-index map (row oy == row 8-oy)
__device__ constexpr int QIDX5[5][9] = {
    {14,13,12,10, 9,10,12,13,14},
    {13,11, 8, 7, 6, 7, 8,11,13},
    {12, 8, 5, 4, 3, 4, 5, 8,12},
    {10, 7, 4, 2, 1, 2, 4, 7,10},
    { 9, 6, 3, 1, 0, 1, 3, 6, 9},
};

__device__ __forceinline__ int reflect_idx(int v) {
    v = (v < 0) ? -v : v;
    return (v >= HH) ? (2 * HH - 2 - v) : v;   // H == W == 256
}

// Unnormalized: u[q] = (1 - q*a) * E^q. Returns 'common'.
__device__ __forceinline__ float make_weights_u(float ddx, float ddy, float* u)
{
    const float d2   = ddx * ddx + ddy * ddy;
    const float dist = sqrtf(d2);
    const float s    = SIGMA_MIN + SIGMA_RANGE * (dist * INV_DIAG);
    const float s2   = s * s;
    const float a    = 0.5f / s2;
    const float common = -dist * sqrtf(s) * __fdividef(1.0f, PI_F * s2 * s2);

    const float E   = __expf(-a);
    const float E2  = E  * E,  E4  = E2  * E2, E5  = E4  * E;
    const float E8  = E4 * E4, E9  = E8  * E,  E10 = E8  * E2;
    const float E13 = E8 * E5, E16 = E8  * E8, E17 = E16 * E;
    const float E18 = E16* E2, E20 = E16 * E4, E25 = E16 * E9;
    const float E32 = E16 * E16;

    u[0]  = 1.0f;
    u[1]  = fmaf( -1.0f, a, 1.0f) * E;
    u[2]  = fmaf( -2.0f, a, 1.0f) * E2;
    u[3]  = fmaf( -4.0f, a, 1.0f) * E4;
    u[4]  = fmaf( -5.0f, a, 1.0f) * E5;
    u[5]  = fmaf( -8.0f, a, 1.0f) * E8;
    u[6]  = fmaf( -9.0f, a, 1.0f) * E9;
    u[7]  = fmaf(-10.0f, a, 1.0f) * E10;
    u[8]  = fmaf(-13.0f, a, 1.0f) * E13;
    u[9]  = fmaf(-16.0f, a, 1.0f) * E16;
    u[10] = fmaf(-17.0f, a, 1.0f) * E17;
    u[11] = fmaf(-18.0f, a, 1.0f) * E18;
    u[12] = fmaf(-20.0f, a, 1.0f) * E20;
    u[13] = fmaf(-25.0f, a, 1.0f) * E25;
    u[14] = fmaf(-32.0f, a, 1.0f) * E32;
    return common;
}

// 64-thread CTAs, occ 16 (64 regs x 64 thr x 16 = 64K regs) -> 2048 CTAs, fine-grained
__global__ __launch_bounds__(TXL * TYL, 16)
void adaptive_log_conv(const float* __restrict__ x,
                       const float* __restrict__ foa,
                       float* __restrict__ out)
{
    __shared__ __align__(16) float pr[CC][4][TH][SXP];  // 7.3 KB paired-row sums
    __shared__ __align__(16) float mid[CC][TH][SXP];    // 1.8 KB middle rows

    const int b   = blockIdx.z;
    const int bx0 = blockIdx.x * TW;
    const int by0 = blockIdx.y * TH;
    const int lx  = threadIdx.x;      // 0..31
    const int ly  = threadIdx.y;      // 0..1
    const int tid = ly * TXL + lx;    // 0..63

    const float* xb = x + (size_t)b * CC * HH * WW;

    // ======== pr central: 384 float4 units = 64 thr x (2 'a' x 3 ch) ========
    {
        const int v   = tid & 15;             // float4 col 0..15
        const int row = (tid >> 4) & 1;       // 0..1
        const int a0  = tid >> 5;             // 0 or 1
        const int a1  = a0 + 2;               // 2 or 3
        const int ga0 = reflect_idx(by0 + row + a0 - PAD);
        const int gb0 = reflect_idx(by0 + row + 4 - a0);   // mirrored row (8-a0)-PAD
        const int ga1 = reflect_idx(by0 + row + a1 - PAD);
        const int gb1 = reflect_idx(by0 + row + 4 - a1);
        const int col = bx0 + 4 * v;
        const int sc  = 4 + 4 * v;
        #pragma unroll
        for (int c = 0; c < CC; c++) {
            const float* base = xb + c * (HH * WW);
            float4 p = *(const float4*)(base + ga0 * WW + col);
            float4 q = *(const float4*)(base + gb0 * WW + col);
            float4 r;
            r.x = p.x + q.x; r.y = p.y + q.y; r.z = p.z + q.z; r.w = p.w + q.w;
            *(float4*)&pr[c][a0][row][sc] = r;

            p = *(const float4*)(base + ga1 * WW + col);
            q = *(const float4*)(base + gb1 * WW + col);
            r.x = p.x + q.x; r.y = p.y + q.y; r.z = p.z + q.z; r.w = p.w + q.w;
            *(float4*)&pr[c][a1][row][sc] = r;
        }
    }

    // ======== pr halo: 192 scalars = 64 thr x 3 ch; (h,row,a) per-thread const ====
    {
        const int h    = tid & 7;
        const int rowh = (tid >> 3) & 1;
        const int ah   = tid >> 4;            // 0..3
        const int s    = (h < 4) ? h : h + 64;
        const int gx   = reflect_idx(bx0 + s - PAD);
        const int gy1  = reflect_idx(by0 + rowh + ah - PAD);
        const int gy2  = reflect_idx(by0 + rowh + 4 - ah);
        #pragma unroll
        for (int c = 0; c < CC; c++) {
            const float* base = xb + c * (HH * WW);
            pr[c][ah][rowh][s] = base[gy1 * WW + gx] + base[gy2 * WW + gx];
        }
    }

    // ======== mid central: 96 float4 units ========
    {
        const int v   = tid & 15;
        const int row = (tid >> 4) & 1;
        const int c0  = tid >> 5;             // 0 or 1
        const int col = bx0 + 4 * v;
        const int gy  = (by0 + row) * WW;     // middle rows always in-bounds in y
        const float4 p = *(const float4*)(xb + c0 * (HH * WW) + gy + col);
        *(float4*)&mid[c0][row][4 + 4 * v] = p;
        if (tid < 32) {                        // c = 2 (warp 0, uniform)
            const float4 p2 = *(const float4*)(xb + 2 * (HH * WW) + gy + col);
            *(float4*)&mid[2][row][4 + 4 * v] = p2;
        }
    }

    // ======== mid halo: 48 scalars (tid < 48) ========
    if (tid < 48) {
        const int h   = tid & 7;
        const int row = (tid >> 3) & 1;
        const int c   = tid >> 4;             // 0..2
        const int s   = (h < 4) ? h : h + 64;
        const int gx  = reflect_idx(bx0 + s - PAD);
        mid[c][row][s] = xb[c * (HH * WW) + (by0 + row) * WW + gx];
    }

    // ======== weight generation (overlaps in-flight LDGs) ========
    const int px0 = bx0 + PXT * lx;
    const int py  = by0 + ly;
    const float fx  = foa[b * 2 + 0];
    const float fy  = foa[b * 2 + 1];
    const float ddy = (float)py - fy;

    float w0[15], w1[15];
    const float common0 = make_weights_u((float)(px0    ) - fx, ddy, w0);
    const float common1 = make_weights_u((float)(px0 + 1) - fx, ddy, w1);

    __syncthreads();   // syncs only 2 warps

    // ======== convolution: 5 effective rows x 3 channels, 2 px/thread ========
    float acc[CC][PXT];
    #pragma unroll
    for (int c = 0; c < CC; c++) { acc[c][0] = 0.0f; acc[c][1] = 0.0f; }

    #pragma unroll
    for (int c = 0; c < CC; c++) {
        #pragma unroll
        for (int a = 0; a < 5; a++) {
            const float* row = (a < 4) ? &pr[c][a][ly][PXT * lx]
                                       : &mid[c][ly][PXT * lx];
            const float2 p0 = *(const float2*)(row + 0);
            const float2 p1 = *(const float2*)(row + 2);
            const float2 p2 = *(const float2*)(row + 4);
            const float2 p3 = *(const float2*)(row + 6);
            const float2 p4 = *(const float2*)(row + 8);
            float t[10];
            t[0] = p0.x; t[1] = p0.y; t[2] = p1.x; t[3] = p1.y;
            t[4] = p2.x; t[5] = p2.y; t[6] = p3.x; t[7] = p3.y;
            t[8] = p4.x; t[9] = p4.y;
            #pragma unroll
            for (int ox = 0; ox < KW; ox++) {
                const int q = QIDX5[a][ox];
                acc[c][0] = fmaf(t[ox    ], w0[q], acc[c][0]);
                acc[c][1] = fmaf(t[ox + 1], w1[q], acc[c][1]);
            }
        }
    }

    float* ob = out + (size_t)b * CC * HH * WW;
    #pragma unroll
    for (int c = 0; c < CC; c++) {
        float2 r;
        r.x = acc[c][0] * common0;
        r.y = acc[c][1] * common1;
        *(float2*)&ob[(c * HH + py) * WW + px0] = r;
    }
}

extern "C" void kernel_launch(void* const* d_in, const int* in_sizes, int n_in,
                              void* d_out, int out_size)
{
    const float* x   = (const float*)d_in[0];
    const float* foa = (const float*)d_in[1];
    float* out = (float*)d_out;

    dim3 block(TXL, TYL, 1);
    dim3 grid(WW / TW, HH / TH, 4);   // 4 x 128 x 4 = 2048 CTAs x 64 threads
    adaptive_log_conv<<<grid, block>>>(x, foa, out);
}